// round 1
// baseline (speedup 1.0000x reference)
#include <cuda_runtime.h>
#include <cstdint>

#define NHID   1024
#define LSTEPS 1024
#define TPB    256          // threads per CTA
#define NPT    4            // neurons per thread (contiguous, float4)
#define NWARP  (TPB / 32)   // 8 warps

// One CTA = one batch row. Each thread owns 4 contiguous neurons n = 4*tid+q.
// Spike state s_{t-1} is exchanged via a double-buffered 1024-bit mask in smem:
//   mask[buf][warp] is a uint4; component q, bit l  ->  neuron j = 128*warp + 4*l + q.
// A shared "last step with any spike" stamp lets the (expected-common) zero-spike
// case skip the whole mask scan.
__global__ __launch_bounds__(TPB)
void coesn_kernel(const float* __restrict__ x,      // (B, L)   [N_INP==1]
                  const float* __restrict__ x2h,    // (NHID)
                  const float* __restrict__ h2h,    // (NHID, NHID) row-major
                  const float* __restrict__ bias,   // (NHID)
                  const float* __restrict__ gamma_, // (NHID)
                  const float* __restrict__ eps_,   // (NHID)
                  const float* __restrict__ sgain,  // scalar
                  float* __restrict__ out)          // (B, 2*NHID)
{
    __shared__ float xs[LSTEPS];
    __shared__ uint4 smask[2][NWARP];
    __shared__ int   sflag;     // last step index that produced >=1 spike

    const int tid  = threadIdx.x;
    const int b    = blockIdx.x;
    const int warp = tid >> 5;
    const int lane = tid & 31;

    // Stage this row's input (1024 floats = 4 KB) into smem.
    ((float4*)xs)[tid] = ((const float4*)(x + (size_t)b * LSTEPS))[tid];

    // Zero both mask buffers (s_{-1} == 0), init spike stamp.
    if (tid < 2 * NWARP * 4) ((unsigned*)smask)[tid] = 0u;
    if (tid == 0) sflag = -2;

    // Per-neuron constants.
    const float4 w4 = ((const float4*)x2h)[tid];
    const float4 b4 = ((const float4*)bias)[tid];
    const float4 g4 = ((const float4*)gamma_)[tid];
    const float4 e4 = ((const float4*)eps_)[tid];
    const float  sg = *sgain;

    float wv[4] = {w4.x, w4.y, w4.z, w4.w};
    float bv[4] = {b4.x, b4.y, b4.z, b4.w};
    float gv[4] = {g4.x, g4.y, g4.z, g4.w};
    float ev[4] = {e4.x, e4.y, e4.z, e4.w};

    const float dt      = 0.01f;
    const float inv_tm  = 0.05f;                 // 1 / LIF_TAU_M (=20)
    const float decay   = expf(-0.001f);         // exp(-dt/TAU_FILTER)
    const float rdecay  = expf(-0.04f);          // exp(-dt/TAU_REF)

    float hy[4]   = {0,0,0,0};
    float hz[4]   = {0,0,0,0};
    float ref[4]  = {0,0,0,0};
    float lifv[4] = {0,0,0,0};
    float ft[4]   = {0,0,0,0};
    float fts[4]  = {0,0,0,0};

    const float4* __restrict__ h4 = (const float4*)h2h;

    __syncthreads();

    for (int t = 0; t < LSTEPS; ++t) {
        const int rb = t & 1;

        // ---- recurrent input: sum over spiking neurons j of h2h[j, n] ----
        float accv[4] = {0.f, 0.f, 0.f, 0.f};
        if (sflag == t - 1) {            // somebody spiked last step
            #pragma unroll
            for (int i = 0; i < NWARP; ++i) {
                uint4 mw = smask[rb][i];
                unsigned ws[4] = {mw.x, mw.y, mw.z, mw.w};
                #pragma unroll
                for (int q = 0; q < 4; ++q) {
                    unsigned w_ = ws[q];
                    while (w_) {
                        int l = __ffs(w_) - 1;
                        w_ &= w_ - 1;
                        int j = i * 128 + l * 4 + q;       // spiking neuron index
                        float4 hv = __ldg(&h4[(size_t)j * (NHID / 4) + tid]);
                        accv[0] += hv.x; accv[1] += hv.y;
                        accv[2] += hv.z; accv[3] += hv.w;
                    }
                }
            }
        }

        const float xt = xs[t];
        unsigned bal[4];
        bool any = false;

        #pragma unroll
        for (int q = 0; q < 4; ++q) {
            // I = x_t * x2h + s@h2h + bias
            float I = xt * wv[q] + accv[q] + bv[q];
            // LIF membrane
            lifv[q] = lifv[q] + dt * (I - lifv[q] * inv_tm);
            float ls = (lifv[q] > 1.0f) ? 1.0f : 0.0f;
            lifv[q] -= ls;                                   // THETA_LIF = 1
            // RF oscillator
            hz[q] = hz[q] + dt * (sg * ls - gv[q] * hy[q] - ev[q] * hz[q]);
            hy[q] = hy[q] + dt * hz[q];
            // RF spike
            bool sn = ((hy[q] - 1.0f) - ref[q]) > 0.0f;      // THETA_RF = 1
            float snf = sn ? 1.0f : 0.0f;
            ref[q] = ref[q] * rdecay + snf;
            ft[q]  = ft[q] * decay + snf;
            fts[q] += ft[q];
            bal[q] = __ballot_sync(0xffffffffu, sn);
            any = any || (bal[q] != 0u);
        }

        if (lane == 0) {
            smask[rb ^ 1][warp] = make_uint4(bal[0], bal[1], bal[2], bal[3]);
            if (any) sflag = t;          // benign same-value race across warps
        }
        __syncthreads();
    }

    // ---- epilogue: out = concat(fts / L, ft) ----
    const float invL = 1.0f / (float)LSTEPS;     // exact power of two
    #pragma unroll
    for (int q = 0; q < 4; ++q) {
        int n = tid * 4 + q;
        out[(size_t)b * (2 * NHID) + n]        = fts[q] * invL;
        out[(size_t)b * (2 * NHID) + NHID + n] = ft[q];
    }
}

extern "C" void kernel_launch(void* const* d_in, const int* in_sizes, int n_in,
                              void* d_out, int out_size)
{
    const float* x     = (const float*)d_in[0];
    const float* x2h   = (const float*)d_in[1];
    const float* h2h   = (const float*)d_in[2];
    const float* bias  = (const float*)d_in[3];
    const float* gam   = (const float*)d_in[4];
    const float* eps   = (const float*)d_in[5];
    const float* sg    = (const float*)d_in[6];

    const int B = in_sizes[0] / LSTEPS;          // N_INP == 1
    coesn_kernel<<<B, TPB>>>(x, x2h, h2h, bias, gam, eps, sg, (float*)d_out);
}

// round 2
// speedup vs baseline: 2.0025x; 2.0025x over previous
#include <cuda_runtime.h>
#include <cstdint>
#include <math.h>

#define NHID   1024
#define LSTEPS 1024
#define TPB    128
#define NPT    8            // neurons per thread (contiguous)
#define NPAIR  4            // f32x2 pairs per thread
#define NWARP  (TPB / 32)   // 4 warps

typedef unsigned long long u64;

// ---- packed f32x2 ops (sm_100+; one SASS instruction per 2 lanes) ----
__device__ __forceinline__ float2 ffma2(float2 a, float2 b, float2 c) {
    float2 d;
    asm("fma.rn.f32x2 %0, %1, %2, %3;"
        : "=l"(*(u64*)&d) : "l"(*(u64*)&a), "l"(*(u64*)&b), "l"(*(u64*)&c));
    return d;
}
__device__ __forceinline__ float2 fadd2(float2 a, float2 b) {
    float2 d;
    asm("add.rn.f32x2 %0, %1, %2;"
        : "=l"(*(u64*)&d) : "l"(*(u64*)&a), "l"(*(u64*)&b));
    return d;
}
__device__ __forceinline__ float2 fmul2(float2 a, float2 b) {
    float2 d;
    asm("mul.rn.f32x2 %0, %1, %2;"
        : "=l"(*(u64*)&d) : "l"(*(u64*)&a), "l"(*(u64*)&b));
    return d;
}

// One CTA = one batch row (B=2048 CTAs). Thread owns neurons [8*tid, 8*tid+8)
// as 4 f32x2 pairs. Spike exchange: per-warp 256-bit mask, written ONLY on
// spiking steps, validated by double-buffered per-warp step stamps.
// smask[buf][w][q] bit l  ->  neuron 256*w + 8*l + q.
__global__ __launch_bounds__(TPB, 4)
void coesn_kernel(const float* __restrict__ x,      // (B, L)
                  const float* __restrict__ x2h,    // (NHID)
                  const float* __restrict__ h2h,    // (NHID, NHID)
                  const float* __restrict__ bias,   // (NHID)
                  const float* __restrict__ gamma_, // (NHID)
                  const float* __restrict__ eps_,   // (NHID)
                  const float* __restrict__ sgain,  // scalar
                  float* __restrict__ out)          // (B, 2*NHID)
{
    __shared__ float    xs[LSTEPS];
    __shared__ unsigned smask[2][NWARP][NPT];
    __shared__ int      wstamp[2][NWARP];
    __shared__ int      sAny[2];

    const int tid  = threadIdx.x;
    const int b    = blockIdx.x;
    const int warp = tid >> 5;
    const int lane = tid & 31;

    // Stage this row's 1024 inputs into smem (two float4 passes).
    {
        const float4* xr = (const float4*)(x + (size_t)b * LSTEPS);
        ((float4*)xs)[tid]       = xr[tid];
        ((float4*)xs)[tid + TPB] = xr[tid + TPB];
    }
    if (tid < 2 * NWARP) ((int*)wstamp)[tid] = -7;
    if (tid < 2)         sAny[tid] = -7;

    // ---- constants ----
    const float dt = 0.01f;
    const float A  = 1.0f - dt / 20.0f;          // LIF decay
    const float sg = *sgain;
    const float RD = expf(-dt / 0.25f);          // refractory decay
    const float FD = expf(-dt / 10.0f);          // filter decay

    const float2 A2     = make_float2(A, A);
    const float2 DT2    = make_float2(dt, dt);
    const float2 NDTSG2 = make_float2(-dt * sg, -dt * sg);
    const float2 RD2    = make_float2(RD, RD);
    const float2 FD2    = make_float2(FD, FD);
    const float2 NEG1_2 = make_float2(-1.0f, -1.0f);

    float2 W2[NPAIR], B2[NPAIR], EZ2[NPAIR], GN2[NPAIR];
    {
        const float4* p;
        p = (const float4*)x2h;
        float4 a = p[tid*2], c = p[tid*2+1];
        W2[0] = make_float2(dt*a.x, dt*a.y); W2[1] = make_float2(dt*a.z, dt*a.w);
        W2[2] = make_float2(dt*c.x, dt*c.y); W2[3] = make_float2(dt*c.z, dt*c.w);
        p = (const float4*)bias;
        a = p[tid*2]; c = p[tid*2+1];
        B2[0] = make_float2(dt*a.x, dt*a.y); B2[1] = make_float2(dt*a.z, dt*a.w);
        B2[2] = make_float2(dt*c.x, dt*c.y); B2[3] = make_float2(dt*c.z, dt*c.w);
        p = (const float4*)eps_;
        a = p[tid*2]; c = p[tid*2+1];
        EZ2[0] = make_float2(1.f-dt*a.x, 1.f-dt*a.y); EZ2[1] = make_float2(1.f-dt*a.z, 1.f-dt*a.w);
        EZ2[2] = make_float2(1.f-dt*c.x, 1.f-dt*c.y); EZ2[3] = make_float2(1.f-dt*c.z, 1.f-dt*c.w);
        p = (const float4*)gamma_;
        a = p[tid*2]; c = p[tid*2+1];
        GN2[0] = make_float2(-dt*a.x, -dt*a.y); GN2[1] = make_float2(-dt*a.z, -dt*a.w);
        GN2[2] = make_float2(-dt*c.x, -dt*c.y); GN2[3] = make_float2(-dt*c.z, -dt*c.w);
    }

    float2 lif2[NPAIR], hy2[NPAIR], hz2[NPAIR], ref2[NPAIR], ft2[NPAIR], fts2[NPAIR];
    #pragma unroll
    for (int p = 0; p < NPAIR; ++p) {
        lif2[p] = make_float2(0.f, 0.f); hy2[p] = make_float2(0.f, 0.f);
        hz2[p]  = make_float2(0.f, 0.f); ref2[p] = make_float2(0.f, 0.f);
        ft2[p]  = make_float2(0.f, 0.f); fts2[p] = make_float2(0.f, 0.f);
    }

    __syncthreads();

    int wAct = 0;   // this warp has ever RF-spiked

    #pragma unroll 1
    for (int t = 0; t < LSTEPS; ++t) {
        const int rb = t & 1;

        const float  xt  = xs[t];
        const float2 XT2 = make_float2(xt, xt);

        // I_scaled = dt * (xt*x2h + bias)    (recurrent term added below, rare)
        float2 I2[NPAIR];
        #pragma unroll
        for (int p = 0; p < NPAIR; ++p) I2[p] = ffma2(XT2, W2[p], B2[p]);

        // ---- rare: recurrent gather of h2h rows of spiking neurons ----
        if (sAny[rb] == t - 1) {
            float2 acc[NPAIR];
            #pragma unroll
            for (int p = 0; p < NPAIR; ++p) acc[p] = make_float2(0.f, 0.f);
            #pragma unroll
            for (int i = 0; i < NWARP; ++i) {
                if (wstamp[rb][i] == t - 1) {
                    #pragma unroll
                    for (int q = 0; q < NPT; ++q) {
                        unsigned m = smask[rb][i][q];
                        while (m) {
                            int l = __ffs(m) - 1; m &= m - 1;
                            int j = i * 256 + l * 8 + q;
                            const float4* hp = (const float4*)(h2h + (size_t)j * NHID + tid * NPT);
                            float4 h0 = __ldg(hp), h1 = __ldg(hp + 1);
                            acc[0].x += h0.x; acc[0].y += h0.y;
                            acc[1].x += h0.z; acc[1].y += h0.w;
                            acc[2].x += h1.x; acc[2].y += h1.y;
                            acc[3].x += h1.z; acc[3].y += h1.w;
                        }
                    }
                }
            }
            #pragma unroll
            for (int p = 0; p < NPAIR; ++p) I2[p] = ffma2(DT2, acc[p], I2[p]);
        }

        // ---- per-neuron dynamics (packed) ----
        bool q_[NPT];
        #pragma unroll
        for (int p = 0; p < NPAIR; ++p) {
            lif2[p] = ffma2(lif2[p], A2, I2[p]);             // v = v*A + dt*I
            const bool l0 = lif2[p].x > 1.0f;
            const bool l1 = lif2[p].y > 1.0f;
            float2 ms = make_float2(l0 ? -1.0f : 0.0f, l1 ? -1.0f : 0.0f);
            lif2[p] = fadd2(lif2[p], ms);                    // soft reset
            float2 k  = fmul2(ms, NDTSG2);                   // +dt*sg on spike
            hz2[p] = ffma2(hz2[p], EZ2[p], ffma2(GN2[p], hy2[p], k));
            hy2[p] = ffma2(DT2, hz2[p], hy2[p]);
            float2 e = fadd2(hy2[p], NEG1_2);                // hy - 1
            q_[2*p]   = e.x > ref2[p].x;                     // (hy-1) > ref
            q_[2*p+1] = e.y > ref2[p].y;
        }

        const bool anyspk = q_[0]|q_[1]|q_[2]|q_[3]|q_[4]|q_[5]|q_[6]|q_[7];
        const unsigned bal = __ballot_sync(0xffffffffu, anyspk);

        if (bal) {                                    // rare: publish spike mask
            wAct = 1;
            unsigned bq[NPT];
            #pragma unroll
            for (int q = 0; q < NPT; ++q) bq[q] = __ballot_sync(0xffffffffu, q_[q]);
            if (lane == 0) {
                #pragma unroll
                for (int q = 0; q < NPT; ++q) smask[rb ^ 1][warp][q] = bq[q];
                wstamp[rb ^ 1][warp] = t;
                sAny[rb ^ 1] = t;                     // benign same-value race
            }
        }

        if (wAct) {                                   // ref/ft/fts stay 0 until first spike
            #pragma unroll
            for (int p = 0; p < NPAIR; ++p) {
                float2 sn = make_float2(q_[2*p] ? 1.0f : 0.0f, q_[2*p+1] ? 1.0f : 0.0f);
                ref2[p] = ffma2(ref2[p], RD2, sn);
                ft2[p]  = ffma2(ft2[p],  FD2, sn);
                fts2[p] = fadd2(fts2[p], ft2[p]);
            }
        }

        __syncthreads();
    }

    // ---- epilogue: out = concat(fts / L, ft) ----
    const float invL = 1.0f / (float)LSTEPS;
    float* o0 = out + (size_t)b * (2 * NHID) + tid * NPT;
    float* o1 = o0 + NHID;
    float4 m0 = make_float4(fts2[0].x*invL, fts2[0].y*invL, fts2[1].x*invL, fts2[1].y*invL);
    float4 m1 = make_float4(fts2[2].x*invL, fts2[2].y*invL, fts2[3].x*invL, fts2[3].y*invL);
    float4 f0 = make_float4(ft2[0].x, ft2[0].y, ft2[1].x, ft2[1].y);
    float4 f1 = make_float4(ft2[2].x, ft2[2].y, ft2[3].x, ft2[3].y);
    ((float4*)o0)[0] = m0; ((float4*)o0)[1] = m1;
    ((float4*)o1)[0] = f0; ((float4*)o1)[1] = f1;
}

extern "C" void kernel_launch(void* const* d_in, const int* in_sizes, int n_in,
                              void* d_out, int out_size)
{
    const float* x    = (const float*)d_in[0];
    const float* x2h  = (const float*)d_in[1];
    const float* h2h  = (const float*)d_in[2];
    const float* bias = (const float*)d_in[3];
    const float* gam  = (const float*)d_in[4];
    const float* eps  = (const float*)d_in[5];
    const float* sg   = (const float*)d_in[6];

    const int B = in_sizes[0] / LSTEPS;   // N_INP == 1
    coesn_kernel<<<B, TPB>>>(x, x2h, h2h, bias, gam, eps, sg, (float*)d_out);
}